// round 13
// baseline (speedup 1.0000x reference)
#include <cuda_runtime.h>
#include <cuda_fp16.h>
#include <math.h>
#include <stdint.h>

// Problem constants
#define T 8192
#define D 1024
#define H 4096
#define E 8
#define NE 9        // 8 routed + shared pseudo-expert

// GEMM tiling
#define TM 128
#define TN 256
#define KC 64       // fp16 K elements per chunk: 128B rows (SW128 swizzle)
#define NTHR 512

// SMEM layout (relative to 1024-aligned base)
#define OFF_ROWA  0          // int[128]
#define OFF_ROWS  512        // int[128]
#define OFF_W     1024       // float[128]
#define OFF_A     2048       // 2 x 16KB
#define OFF_B     34816      // 2 x 32KB
#define SMEM_CORE 100352
#define SMEM_SZ   (SMEM_CORE + 1024)

#define SWZ(off) ((off) ^ (((off) >> 3) & 0x70))

// ---------------- static device scratch (allocation-free) -------------------
__device__ int    g_cnt[NE];
__device__ int    g_pair_tok[NE * T];
__device__ int    g_pair_hidx[NE * T];
__device__ float  g_pair_w[NE * T];
__device__ __half g_xh[(size_t)T * D];         // x fp16  [T][D]
__device__ __half g_w1t[(size_t)NE * H * D];   // per e: [H][D] K-major
__device__ __half g_w2t[(size_t)NE * D * H];   // per e: [D][H] K-major
__device__ __half g_h[(size_t)T * 3 * H];      // activations fp16 (weight-folded)
__device__ float  g_po[(size_t)T * 3 * D];     // per-pair down-proj output

// ---------------- PTX helpers ------------------------------------------------
__device__ __forceinline__ uint32_t smem_u32(const void* p) {
    uint32_t a;
    asm("{ .reg .u64 t; cvta.to.shared.u64 t, %1; cvt.u32.u64 %0, t; }"
        : "=r"(a) : "l"(p));
    return a;
}
#define CP16(s, g) \
    asm volatile("cp.async.cg.shared.global [%0], [%1], 16;" \
                 :: "r"(s), "l"(g) : "memory")
#define CP_COMMIT() asm volatile("cp.async.commit_group;" ::: "memory")
#define CP_WAIT1()  asm volatile("cp.async.wait_group 1;" ::: "memory")
#define CP_WAIT0()  asm volatile("cp.async.wait_group 0;" ::: "memory")

#define LDSM_X4(d0, d1, d2, d3, a) \
    asm volatile("ldmatrix.sync.aligned.m8n8.x4.shared.b16 {%0,%1,%2,%3}, [%4];" \
                 : "=r"(d0), "=r"(d1), "=r"(d2), "=r"(d3) : "r"(a))

__device__ __forceinline__ void mma16816(float* c, const uint32_t* a,
                                         const uint32_t* b) {
    asm volatile(
        "mma.sync.aligned.m16n8k16.row.col.f32.f16.f16.f32 "
        "{%0,%1,%2,%3}, {%4,%5,%6,%7}, {%8,%9}, {%0,%1,%2,%3};"
        : "+f"(c[0]), "+f"(c[1]), "+f"(c[2]), "+f"(c[3])
        : "r"(a[0]), "r"(a[1]), "r"(a[2]), "r"(a[3]), "r"(b[0]), "r"(b[1]));
}

// ---------------- kernel: reset counters -------------------------------------
__global__ void zero_cnt_kernel() {
    int i = threadIdx.x;
    if (i < NE) g_cnt[i] = (i == E) ? T : 0;
}

// ---------------- kernel: router (warp per token) ----------------------------
__global__ void router_kernel(const float* __restrict__ x,
                              const float* __restrict__ rw) {
    int warp = (blockIdx.x * blockDim.x + threadIdx.x) >> 5;
    int lane = threadIdx.x & 31;
    if (warp >= T) return;

    const float* xr = x + (size_t)warp * D;
    float acc[E];
#pragma unroll
    for (int e = 0; e < E; e++) acc[e] = 0.f;

    for (int d = lane; d < D; d += 32) {
        float xv = xr[d];
        const float4* r4 = (const float4*)(rw + (size_t)d * E);
        float4 r0 = r4[0], r1 = r4[1];
        acc[0] += xv * r0.x; acc[1] += xv * r0.y;
        acc[2] += xv * r0.z; acc[3] += xv * r0.w;
        acc[4] += xv * r1.x; acc[5] += xv * r1.y;
        acc[6] += xv * r1.z; acc[7] += xv * r1.w;
    }
#pragma unroll
    for (int o = 16; o; o >>= 1)
#pragma unroll
        for (int e = 0; e < E; e++)
            acc[e] += __shfl_xor_sync(0xFFFFFFFFu, acc[e], o);

    if (lane == 0) {
        float mx = acc[0];
#pragma unroll
        for (int e = 1; e < E; e++) mx = fmaxf(mx, acc[e]);
        float p[E];
#pragma unroll
        for (int e = 0; e < E; e++) p[e] = expf(acc[e] - mx);

        int i0 = 0; float v0 = p[0];
#pragma unroll
        for (int e = 1; e < E; e++) if (p[e] > v0) { v0 = p[e]; i0 = e; }
        int i1 = (i0 == 0) ? 1 : 0; float v1 = p[i1];
#pragma unroll
        for (int e = 0; e < E; e++)
            if (e != i0 && p[e] > v1) { v1 = p[e]; i1 = e; }

        float s = v0 + v1;
        float w0 = v0 / s, w1 = v1 / s;

        int s0 = atomicAdd(&g_cnt[i0], 1);
        g_pair_tok [i0 * T + s0] = warp;
        g_pair_hidx[i0 * T + s0] = warp * 3 + 0;
        g_pair_w   [i0 * T + s0] = w0;

        int s1 = atomicAdd(&g_cnt[i1], 1);
        g_pair_tok [i1 * T + s1] = warp;
        g_pair_hidx[i1 * T + s1] = warp * 3 + 1;
        g_pair_w   [i1 * T + s1] = w1;

        g_pair_tok [E * T + warp] = warp;
        g_pair_hidx[E * T + warp] = warp * 3 + 2;
        g_pair_w   [E * T + warp] = 1.0f;
    }
}

// ---------------- kernel: x -> fp16 ------------------------------------------
__global__ void cvt_x_kernel(const float* __restrict__ x) {
    int i = blockIdx.x * blockDim.x + threadIdx.x;   // over T*D/4
    float4 v = ((const float4*)x)[i];
    __half2* o = (__half2*)g_xh;
    o[i * 2 + 0] = __floats2half2_rn(v.x, v.y);
    o[i * 2 + 1] = __floats2half2_rn(v.z, v.w);
}

// ---------------- kernels: transpose+convert weights to fp16 K-major --------
__device__ __forceinline__ void transpose_tile(const float* __restrict__ in,
                                               __half* __restrict__ outp,
                                               int R, int C) {
    __shared__ float tile[32][33];
    int c0 = blockIdx.x * 32, r0 = blockIdx.y * 32;
    int tx = threadIdx.x, ty = threadIdx.y;   // block (32, 8)
#pragma unroll
    for (int j = 0; j < 32; j += 8)
        tile[ty + j][tx] = in[(size_t)(r0 + ty + j) * C + (c0 + tx)];
    __syncthreads();
#pragma unroll
    for (int j = 0; j < 32; j += 8)
        outp[(size_t)(c0 + ty + j) * R + (r0 + tx)] = __float2half(tile[tx][ty + j]);
}
__global__ void tcvt_w1_kernel(const float* __restrict__ w1,
                               const float* __restrict__ sw1) {
    int e = blockIdx.z;
    const float* in = (e < E) ? (w1 + (size_t)e * D * H) : sw1;  // [D, H]
    transpose_tile(in, g_w1t + (size_t)e * H * D, D, H);          // -> [H, D]
}
__global__ void tcvt_w2_kernel(const float* __restrict__ w2,
                               const float* __restrict__ sw2) {
    int e = blockIdx.z;
    const float* in = (e < E) ? (w2 + (size_t)e * H * D) : sw2;  // [H, D]
    transpose_tile(in, g_w2t + (size_t)e * D * H, H, D);          // -> [D, H]
}

// ---------------- main grouped HMMA GEMM -------------------------------------
// UP:  g_h[hidx, n] = w * silu( xh[tok, :] . w1t[e][n, :] ),  K = D
// DN:  g_po[hidx, n] = g_h[hidx, :] . w2t[e][n, :],           K = H
// Tile: 128(M) x 256(N), 512 threads, warp grid 2(M) x 8(N), warp tile 64x32.
template <bool UP>
__global__ void __launch_bounds__(NTHR, 1) moe_mma_kernel() {
    constexpr int KDIM = UP ? D : H;
    constexpr int NC = KDIM / KC;

    extern __shared__ char smem_raw[];

    const int e = blockIdx.z;
    const int cnt = g_cnt[e];
    const int m0 = blockIdx.y * TM;
    if (m0 >= cnt) return;
    const int n0 = blockIdx.x * TN;

    const int tid = threadIdx.x, wid = tid >> 5, lane = tid & 31;
    const int grp = lane >> 2, qp = lane & 3;
    const int warp_m = (wid & 1) * 64;     // 2 warps along M (64 rows each)
    const int warp_n = (wid >> 1) * 32;    // 8 warps along N (32 cols each)

    uint32_t sb_raw = smem_u32(smem_raw);
    uint32_t sb = (sb_raw + 1023u) & ~1023u;
    char* sm = smem_raw + (sb - sb_raw);

    int*   rowA = (int*)(sm + OFF_ROWA);
    int*   rowS = (int*)(sm + OFF_ROWS);
    float* rowW = (float*)(sm + OFF_W);
    for (int i = tid; i < TM; i += NTHR) {
        int m = m0 + i;
        int idx = e * T + ((m < cnt) ? m : m0);   // clamp to a valid row
        if (UP) {
            rowA[i] = g_pair_tok[idx];
            rowS[i] = g_pair_hidx[idx];
            rowW[i] = g_pair_w[idx];
        } else {
            rowA[i] = g_pair_hidx[idx];
        }
    }
    __syncthreads();

    const __half* Abase = UP ? g_xh : g_h;
    const __half* Bexp  = (UP ? g_w1t : g_w2t) + (size_t)e * ((size_t)H * D);

    const int lr = tid >> 3, lch = tid & 7;   // 64 load rows per pass, 8 chunks

    // --- ldmatrix per-lane address precompute (SW128 swizzle) ---
    const uint32_t asub = (uint32_t)((lane >> 4) << 4);
    uint32_t arel[4], amask[4];
#pragma unroll
    for (int mt = 0; mt < 4; mt++) {
        uint32_t rr = (uint32_t)((warp_m + mt * 16 + (lane & 15)) * 128);
        arel[mt] = rr;
        amask[mt] = (rr >> 3) & 0x70;
    }
    const int brow = (lane & 7) | ((lane >> 4) << 3);
    const uint32_t bsub = (uint32_t)(((lane >> 3) & 1) << 4);
    uint32_t brel[2], bmask[2];
#pragma unroll
    for (int g = 0; g < 2; g++) {
        uint32_t rr = (uint32_t)((warp_n + g * 16 + brow) * 128);
        brel[g] = rr;
        bmask[g] = (rr >> 3) & 0x70;
    }

    float acc[4][4][4];
#pragma unroll
    for (int mt = 0; mt < 4; mt++)
#pragma unroll
        for (int nt = 0; nt < 4; nt++)
#pragma unroll
            for (int k = 0; k < 4; k++) acc[mt][nt][k] = 0.f;

    // prologue: chunk 0 -> buffer 0
    {
        uint32_t sA = sb + OFF_A, sBb = sb + OFF_B;
#pragma unroll
        for (int it = 0; it < 2; it++) {     // A: 128 rows
            int r = lr + it * 64;
            uint32_t o = SWZ((uint32_t)(r * 128 + lch * 16));
            CP16(sA + o, Abase + (size_t)rowA[r] * KDIM + lch * 8);
        }
#pragma unroll
        for (int it = 0; it < 4; it++) {     // B: 256 rows
            int r = lr + it * 64;
            uint32_t o = SWZ((uint32_t)(r * 128 + lch * 16));
            CP16(sBb + o, Bexp + (size_t)(n0 + r) * KDIM + lch * 8);
        }
        CP_COMMIT();
    }

#pragma unroll 1
    for (int c = 0; c < NC; c++) {
        const int buf = c & 1;
        if (c + 1 < NC) {
            uint32_t sA = sb + OFF_A + (buf ^ 1) * 16384;
            uint32_t sBb = sb + OFF_B + (buf ^ 1) * 32768;
            const int kb = (c + 1) * KC;
#pragma unroll
            for (int it = 0; it < 2; it++) {
                int r = lr + it * 64;
                uint32_t o = SWZ((uint32_t)(r * 128 + lch * 16));
                CP16(sA + o, Abase + (size_t)rowA[r] * KDIM + kb + lch * 8);
            }
#pragma unroll
            for (int it = 0; it < 4; it++) {
                int r = lr + it * 64;
                uint32_t o = SWZ((uint32_t)(r * 128 + lch * 16));
                CP16(sBb + o, Bexp + (size_t)(n0 + r) * KDIM + kb + lch * 8);
            }
            CP_COMMIT();
            CP_WAIT1();
        } else {
            CP_WAIT0();
        }
        __syncthreads();

        const uint32_t aB = sb + OFF_A + buf * 16384;
        const uint32_t bB = sb + OFF_B + buf * 32768;
#pragma unroll
        for (int k16 = 0; k16 < 4; k16++) {
            const uint32_t kby = (uint32_t)(k16 * 32);
            uint32_t bq[4][2];
            {
                uint32_t r0, r1, r2, r3;
                LDSM_X4(r0, r1, r2, r3, bB + brel[0] + ((kby + bsub) ^ bmask[0]));
                bq[0][0] = r0; bq[0][1] = r1; bq[1][0] = r2; bq[1][1] = r3;
                LDSM_X4(r0, r1, r2, r3, bB + brel[1] + ((kby + bsub) ^ bmask[1]));
                bq[2][0] = r0; bq[2][1] = r1; bq[3][0] = r2; bq[3][1] = r3;
            }
#pragma unroll
            for (int mt = 0; mt < 4; mt++) {
                uint32_t af[4];
                LDSM_X4(af[0], af[1], af[2], af[3],
                        aB + arel[mt] + ((kby + asub) ^ amask[mt]));
#pragma unroll
                for (int nt = 0; nt < 4; nt++)
                    mma16816(acc[mt][nt], af, bq[nt]);
            }
        }
        __syncthreads();
    }

    // ---- epilogue ----
    if (UP) {
#pragma unroll
        for (int mt = 0; mt < 4; mt++) {
#pragma unroll
            for (int hf = 0; hf < 2; hf++) {
                int mi = warp_m + mt * 16 + grp + hf * 8;
                if (m0 + mi < cnt) {
                    float w = rowW[mi];
                    __half* dst = g_h + (size_t)rowS[mi] * H + n0 + warp_n + qp * 2;
#pragma unroll
                    for (int nt = 0; nt < 4; nt++) {
                        float y0 = acc[mt][nt][hf * 2 + 0];
                        float y1 = acc[mt][nt][hf * 2 + 1];
                        __half2 v = __floats2half2_rn(w * (y0 / (1.f + __expf(-y0))),
                                                      w * (y1 / (1.f + __expf(-y1))));
                        *(__half2*)(dst + nt * 8) = v;
                    }
                }
            }
        }
    } else {
#pragma unroll
        for (int mt = 0; mt < 4; mt++) {
#pragma unroll
            for (int hf = 0; hf < 2; hf++) {
                int mi = warp_m + mt * 16 + grp + hf * 8;
                if (m0 + mi < cnt) {
                    float* dst = g_po + (size_t)rowA[mi] * D + n0 + warp_n + qp * 2;
#pragma unroll
                    for (int nt = 0; nt < 4; nt++) {
                        float2 v = make_float2(acc[mt][nt][hf * 2 + 0],
                                               acc[mt][nt][hf * 2 + 1]);
                        *(float2*)(dst + nt * 8) = v;
                    }
                }
            }
        }
    }
}

// ---------------- kernel: combine 3 pair-rows per token ----------------------
__global__ void combine_kernel(float* __restrict__ out) {
    int t = blockIdx.x, r = threadIdx.x;      // 256 threads, D/4 float4s
    const float4* po = (const float4*)g_po;
    size_t b = (size_t)t * 768;               // 3 rows * 256 float4
    float4 a = po[b + r];
    float4 c = po[b + 256 + r];
    float4 d = po[b + 512 + r];
    ((float4*)out)[(size_t)t * 256 + r] =
        make_float4(a.x + c.x + d.x, a.y + c.y + d.y,
                    a.z + c.z + d.z, a.w + c.w + d.w);
}

// ---------------- launch -----------------------------------------------------
extern "C" void kernel_launch(void* const* d_in, const int* in_sizes, int n_in,
                              void* d_out, int out_size) {
    const float* x   = (const float*)d_in[0];
    const float* rw  = (const float*)d_in[1];
    const float* w1  = (const float*)d_in[2];
    const float* w2  = (const float*)d_in[3];
    const float* sw1 = (const float*)d_in[4];
    const float* sw2 = (const float*)d_in[5];
    float* out = (float*)d_out;

    cudaFuncSetAttribute(moe_mma_kernel<true>,
                         cudaFuncAttributeMaxDynamicSharedMemorySize, SMEM_SZ);
    cudaFuncSetAttribute(moe_mma_kernel<false>,
                         cudaFuncAttributeMaxDynamicSharedMemorySize, SMEM_SZ);

    zero_cnt_kernel<<<1, 32>>>();
    router_kernel<<<T / 8, 256>>>(x, rw);
    cvt_x_kernel<<<(T * D / 4) / 256, 256>>>(x);
    tcvt_w1_kernel<<<dim3(H / 32, D / 32, NE), dim3(32, 8)>>>(w1, sw1);
    tcvt_w2_kernel<<<dim3(D / 32, H / 32, NE), dim3(32, 8)>>>(w2, sw2);

    moe_mma_kernel<true><<<dim3(H / TN, T / TM, NE), NTHR, SMEM_SZ>>>();
    moe_mma_kernel<false><<<dim3(D / TN, T / TM, NE), NTHR, SMEM_SZ>>>();

    combine_kernel<<<T, 256>>>(out);
}

// round 14
// speedup vs baseline: 1.0740x; 1.0740x over previous
#include <cuda_runtime.h>
#include <cuda_fp16.h>
#include <math.h>
#include <stdint.h>

// Problem constants
#define T 8192
#define D 1024
#define H 4096
#define E 8
#define NE 9        // 8 routed + shared pseudo-expert

// GEMM tiling
#define TM 128
#define TN 128
#define KC 64       // fp16 K elements per chunk: 128B rows (SW128 swizzle)
#define NTHR 256
#define STAGES 3

// SMEM layout (relative to 1024-aligned base)
#define OFF_ROWA  0          // int[128]
#define OFF_ROWS  512        // int[128]
#define OFF_W     1024       // float[128]
#define OFF_A     2048       // 3 stages x (16KB A + 16KB B)
#define STAGE_SZ  32768
#define SMEM_CORE (2048 + STAGES * STAGE_SZ)
#define SMEM_SZ   (SMEM_CORE + 1024)

#define SWZ(off) ((off) ^ (((off) >> 3) & 0x70))

// ---------------- static device scratch (allocation-free) -------------------
__device__ int    g_cnt[NE];
__device__ int    g_pair_tok[NE * T];
__device__ int    g_pair_hidx[NE * T];
__device__ float  g_pair_w[NE * T];
__device__ __half g_xh[(size_t)T * D];         // x fp16  [T][D]
__device__ __half g_w1t[(size_t)NE * H * D];   // per e: [H][D] K-major
__device__ __half g_w2t[(size_t)NE * D * H];   // per e: [D][H] K-major
__device__ __half g_h[(size_t)T * 3 * H];      // activations fp16 (weight-folded)
__device__ float  g_po[(size_t)T * 3 * D];     // per-pair down-proj output

// ---------------- PTX helpers ------------------------------------------------
__device__ __forceinline__ uint32_t smem_u32(const void* p) {
    uint32_t a;
    asm("{ .reg .u64 t; cvta.to.shared.u64 t, %1; cvt.u32.u64 %0, t; }"
        : "=r"(a) : "l"(p));
    return a;
}
#define CP16(s, g) \
    asm volatile("cp.async.cg.shared.global [%0], [%1], 16;" \
                 :: "r"(s), "l"(g) : "memory")
#define CP_COMMIT() asm volatile("cp.async.commit_group;" ::: "memory")
#define CP_WAIT1()  asm volatile("cp.async.wait_group 1;" ::: "memory")
#define CP_WAIT0()  asm volatile("cp.async.wait_group 0;" ::: "memory")

#define LDSM_X4(d0, d1, d2, d3, a) \
    asm volatile("ldmatrix.sync.aligned.m8n8.x4.shared.b16 {%0,%1,%2,%3}, [%4];" \
                 : "=r"(d0), "=r"(d1), "=r"(d2), "=r"(d3) : "r"(a))

__device__ __forceinline__ void mma16816(float* c, const uint32_t* a,
                                         const uint32_t* b) {
    asm volatile(
        "mma.sync.aligned.m16n8k16.row.col.f32.f16.f16.f32 "
        "{%0,%1,%2,%3}, {%4,%5,%6,%7}, {%8,%9}, {%0,%1,%2,%3};"
        : "+f"(c[0]), "+f"(c[1]), "+f"(c[2]), "+f"(c[3])
        : "r"(a[0]), "r"(a[1]), "r"(a[2]), "r"(a[3]), "r"(b[0]), "r"(b[1]));
}

// ---------------- kernel: reset counters -------------------------------------
__global__ void zero_cnt_kernel() {
    int i = threadIdx.x;
    if (i < NE) g_cnt[i] = (i == E) ? T : 0;
}

// ---------------- kernel: router (warp per token) ----------------------------
__global__ void router_kernel(const float* __restrict__ x,
                              const float* __restrict__ rw) {
    int warp = (blockIdx.x * blockDim.x + threadIdx.x) >> 5;
    int lane = threadIdx.x & 31;
    if (warp >= T) return;

    const float* xr = x + (size_t)warp * D;
    float acc[E];
#pragma unroll
    for (int e = 0; e < E; e++) acc[e] = 0.f;

    for (int d = lane; d < D; d += 32) {
        float xv = xr[d];
        const float4* r4 = (const float4*)(rw + (size_t)d * E);
        float4 r0 = r4[0], r1 = r4[1];
        acc[0] += xv * r0.x; acc[1] += xv * r0.y;
        acc[2] += xv * r0.z; acc[3] += xv * r0.w;
        acc[4] += xv * r1.x; acc[5] += xv * r1.y;
        acc[6] += xv * r1.z; acc[7] += xv * r1.w;
    }
#pragma unroll
    for (int o = 16; o; o >>= 1)
#pragma unroll
        for (int e = 0; e < E; e++)
            acc[e] += __shfl_xor_sync(0xFFFFFFFFu, acc[e], o);

    if (lane == 0) {
        float mx = acc[0];
#pragma unroll
        for (int e = 1; e < E; e++) mx = fmaxf(mx, acc[e]);
        float p[E];
#pragma unroll
        for (int e = 0; e < E; e++) p[e] = expf(acc[e] - mx);

        int i0 = 0; float v0 = p[0];
#pragma unroll
        for (int e = 1; e < E; e++) if (p[e] > v0) { v0 = p[e]; i0 = e; }
        int i1 = (i0 == 0) ? 1 : 0; float v1 = p[i1];
#pragma unroll
        for (int e = 0; e < E; e++)
            if (e != i0 && p[e] > v1) { v1 = p[e]; i1 = e; }

        float s = v0 + v1;
        float w0 = v0 / s, w1 = v1 / s;

        int s0 = atomicAdd(&g_cnt[i0], 1);
        g_pair_tok [i0 * T + s0] = warp;
        g_pair_hidx[i0 * T + s0] = warp * 3 + 0;
        g_pair_w   [i0 * T + s0] = w0;

        int s1 = atomicAdd(&g_cnt[i1], 1);
        g_pair_tok [i1 * T + s1] = warp;
        g_pair_hidx[i1 * T + s1] = warp * 3 + 1;
        g_pair_w   [i1 * T + s1] = w1;

        g_pair_tok [E * T + warp] = warp;
        g_pair_hidx[E * T + warp] = warp * 3 + 2;
        g_pair_w   [E * T + warp] = 1.0f;
    }
}

// ---------------- kernel: x -> fp16 ------------------------------------------
__global__ void cvt_x_kernel(const float* __restrict__ x) {
    int i = blockIdx.x * blockDim.x + threadIdx.x;   // over T*D/4
    float4 v = ((const float4*)x)[i];
    __half2* o = (__half2*)g_xh;
    o[i * 2 + 0] = __floats2half2_rn(v.x, v.y);
    o[i * 2 + 1] = __floats2half2_rn(v.z, v.w);
}

// ---------------- kernels: transpose+convert weights to fp16 K-major --------
// 64(r) x 32(c) input tile; half2 stores give full 128B-line output coverage.
__device__ __forceinline__ void transpose_tile(const float* __restrict__ in,
                                               __half* __restrict__ outp,
                                               int R, int C) {
    __shared__ float tile[64][33];
    int c0 = blockIdx.x * 32, r0 = blockIdx.y * 64;
    int tx = threadIdx.x, ty = threadIdx.y;   // block (32, 8)
#pragma unroll
    for (int j = 0; j < 64; j += 8)
        tile[ty + j][tx] = in[(size_t)(r0 + ty + j) * C + (c0 + tx)];
    __syncthreads();
    int base = ty * 32 + tx;
#pragma unroll
    for (int s = 0; s < 4; s++) {
        int idx = s * 256 + base;         // 0..1023
        int oc = idx >> 5;                // 0..31
        int k  = idx & 31;                // 0..31 -> r pairs
        __half2 v = __floats2half2_rn(tile[2 * k][oc], tile[2 * k + 1][oc]);
        *(__half2*)(outp + (size_t)(c0 + oc) * R + r0 + 2 * k) = v;
    }
}
__global__ void tcvt_w1_kernel(const float* __restrict__ w1,
                               const float* __restrict__ sw1) {
    int e = blockIdx.z;
    const float* in = (e < E) ? (w1 + (size_t)e * D * H) : sw1;  // [D, H]
    transpose_tile(in, g_w1t + (size_t)e * H * D, D, H);          // -> [H, D]
}
__global__ void tcvt_w2_kernel(const float* __restrict__ w2,
                               const float* __restrict__ sw2) {
    int e = blockIdx.z;
    const float* in = (e < E) ? (w2 + (size_t)e * H * D) : sw2;  // [H, D]
    transpose_tile(in, g_w2t + (size_t)e * D * H, H, D);          // -> [D, H]
}

// ---------------- main grouped HMMA GEMM -------------------------------------
// UP:  g_h[hidx, n] = w * silu( xh[tok, :] . w1t[e][n, :] ),  K = D
// DN:  g_po[hidx, n] = g_h[hidx, :] . w2t[e][n, :],           K = H
// Tile: 128x128, 256 threads (2x4 warps, warp tile 64x32), 3-stage cp.async.
template <bool UP>
__global__ void __launch_bounds__(NTHR, 2) moe_mma_kernel() {
    constexpr int KDIM = UP ? D : H;
    constexpr int NC = KDIM / KC;

    extern __shared__ char smem_raw[];

    const int e = blockIdx.z;
    const int cnt = g_cnt[e];
    const int m0 = blockIdx.y * TM;
    if (m0 >= cnt) return;
    const int n0 = blockIdx.x * TN;

    const int tid = threadIdx.x, wid = tid >> 5, lane = tid & 31;
    const int grp = lane >> 2, qp = lane & 3;
    const int warp_m = (wid & 1) * 64;     // 2 warps along M (64 rows each)
    const int warp_n = (wid >> 1) * 32;    // 4 warps along N (32 cols each)

    uint32_t sb_raw = smem_u32(smem_raw);
    uint32_t sb = (sb_raw + 1023u) & ~1023u;
    char* sm = smem_raw + (sb - sb_raw);

    int*   rowA = (int*)(sm + OFF_ROWA);
    int*   rowS = (int*)(sm + OFF_ROWS);
    float* rowW = (float*)(sm + OFF_W);
    for (int i = tid; i < TM; i += NTHR) {
        int m = m0 + i;
        int idx = e * T + ((m < cnt) ? m : m0);   // clamp to a valid row
        if (UP) {
            rowA[i] = g_pair_tok[idx];
            rowS[i] = g_pair_hidx[idx];
            rowW[i] = g_pair_w[idx];
        } else {
            rowA[i] = g_pair_hidx[idx];
        }
    }
    __syncthreads();

    const __half* Abase = UP ? g_xh : g_h;
    const __half* Bexp  = (UP ? g_w1t : g_w2t) + (size_t)e * ((size_t)H * D);

    const int lr = tid >> 3, lch = tid & 7;   // 32 load rows per pass, 8 chunks

    // --- ldmatrix per-lane address precompute (SW128 swizzle) ---
    const uint32_t asub = (uint32_t)((lane >> 4) << 4);
    uint32_t arel[4], amask[4];
#pragma unroll
    for (int mt = 0; mt < 4; mt++) {
        uint32_t rr = (uint32_t)((warp_m + mt * 16 + (lane & 15)) * 128);
        arel[mt] = rr;
        amask[mt] = (rr >> 3) & 0x70;
    }
    const int brow = (lane & 7) | ((lane >> 4) << 3);
    const uint32_t bsub = (uint32_t)(((lane >> 3) & 1) << 4);
    uint32_t brel[2], bmask[2];
#pragma unroll
    for (int g = 0; g < 2; g++) {
        uint32_t rr = (uint32_t)((warp_n + g * 16 + brow) * 128);
        brel[g] = rr;
        bmask[g] = (rr >> 3) & 0x70;
    }

    float acc[4][4][4];
#pragma unroll
    for (int mt = 0; mt < 4; mt++)
#pragma unroll
        for (int nt = 0; nt < 4; nt++)
#pragma unroll
            for (int k = 0; k < 4; k++) acc[mt][nt][k] = 0.f;

    // prologue: chunks 0,1 -> stages 0,1
#pragma unroll
    for (int s = 0; s < 2; s++) {
        uint32_t sA = sb + OFF_A + s * STAGE_SZ;
        uint32_t sBb = sA + 16384;
        const int kb = s * KC;
#pragma unroll
        for (int it = 0; it < 4; it++) {
            int r = lr + it * 32;
            uint32_t o = SWZ((uint32_t)(r * 128 + lch * 16));
            CP16(sA + o, Abase + (size_t)rowA[r] * KDIM + kb + lch * 8);
            CP16(sBb + o, Bexp + (size_t)(n0 + r) * KDIM + kb + lch * 8);
        }
        CP_COMMIT();
    }

#pragma unroll 1
    for (int c = 0; c < NC; c++) {
        // retire chunk c's group (chunk c+1 may stay in flight)
        if (c + 1 < NC) CP_WAIT1(); else CP_WAIT0();
        __syncthreads();   // all warps done reading stage (c-1)%3, data c visible

        if (c + 2 < NC) {  // prefetch chunk c+2 into stage (c+2)%3
            int s = (c + 2) % STAGES;
            uint32_t sA = sb + OFF_A + s * STAGE_SZ;
            uint32_t sBb = sA + 16384;
            const int kb = (c + 2) * KC;
#pragma unroll
            for (int it = 0; it < 4; it++) {
                int r = lr + it * 32;
                uint32_t o = SWZ((uint32_t)(r * 128 + lch * 16));
                CP16(sA + o, Abase + (size_t)rowA[r] * KDIM + kb + lch * 8);
                CP16(sBb + o, Bexp + (size_t)(n0 + r) * KDIM + kb + lch * 8);
            }
            CP_COMMIT();
        }

        const uint32_t aB = sb + OFF_A + (c % STAGES) * STAGE_SZ;
        const uint32_t bB = aB + 16384;
#pragma unroll
        for (int k16 = 0; k16 < 4; k16++) {
            const uint32_t kby = (uint32_t)(k16 * 32);
            uint32_t bq[4][2];
            {
                uint32_t r0, r1, r2, r3;
                LDSM_X4(r0, r1, r2, r3, bB + brel[0] + ((kby + bsub) ^ bmask[0]));
                bq[0][0] = r0; bq[0][1] = r1; bq[1][0] = r2; bq[1][1] = r3;
                LDSM_X4(r0, r1, r2, r3, bB + brel[1] + ((kby + bsub) ^ bmask[1]));
                bq[2][0] = r0; bq[2][1] = r1; bq[3][0] = r2; bq[3][1] = r3;
            }
#pragma unroll
            for (int mt = 0; mt < 4; mt++) {
                uint32_t af[4];
                LDSM_X4(af[0], af[1], af[2], af[3],
                        aB + arel[mt] + ((kby + asub) ^ amask[mt]));
#pragma unroll
                for (int nt = 0; nt < 4; nt++)
                    mma16816(acc[mt][nt], af, bq[nt]);
            }
        }
    }

    // ---- epilogue ----
    if (UP) {
#pragma unroll
        for (int mt = 0; mt < 4; mt++) {
#pragma unroll
            for (int hf = 0; hf < 2; hf++) {
                int mi = warp_m + mt * 16 + grp + hf * 8;
                if (m0 + mi < cnt) {
                    float w = rowW[mi];
                    __half* dst = g_h + (size_t)rowS[mi] * H + n0 + warp_n + qp * 2;
#pragma unroll
                    for (int nt = 0; nt < 4; nt++) {
                        float y0 = acc[mt][nt][hf * 2 + 0];
                        float y1 = acc[mt][nt][hf * 2 + 1];
                        __half2 v = __floats2half2_rn(w * (y0 / (1.f + __expf(-y0))),
                                                      w * (y1 / (1.f + __expf(-y1))));
                        *(__half2*)(dst + nt * 8) = v;
                    }
                }
            }
        }
    } else {
#pragma unroll
        for (int mt = 0; mt < 4; mt++) {
#pragma unroll
            for (int hf = 0; hf < 2; hf++) {
                int mi = warp_m + mt * 16 + grp + hf * 8;
                if (m0 + mi < cnt) {
                    float* dst = g_po + (size_t)rowA[mi] * D + n0 + warp_n + qp * 2;
#pragma unroll
                    for (int nt = 0; nt < 4; nt++) {
                        float2 v = make_float2(acc[mt][nt][hf * 2 + 0],
                                               acc[mt][nt][hf * 2 + 1]);
                        *(float2*)(dst + nt * 8) = v;
                    }
                }
            }
        }
    }
}

// ---------------- kernel: combine 3 pair-rows per token ----------------------
__global__ void combine_kernel(float* __restrict__ out) {
    int t = blockIdx.x, r = threadIdx.x;      // 256 threads, D/4 float4s
    const float4* po = (const float4*)g_po;
    size_t b = (size_t)t * 768;               // 3 rows * 256 float4
    float4 a = po[b + r];
    float4 c = po[b + 256 + r];
    float4 d = po[b + 512 + r];
    ((float4*)out)[(size_t)t * 256 + r] =
        make_float4(a.x + c.x + d.x, a.y + c.y + d.y,
                    a.z + c.z + d.z, a.w + c.w + d.w);
}

// ---------------- launch -----------------------------------------------------
extern "C" void kernel_launch(void* const* d_in, const int* in_sizes, int n_in,
                              void* d_out, int out_size) {
    const float* x   = (const float*)d_in[0];
    const float* rw  = (const float*)d_in[1];
    const float* w1  = (const float*)d_in[2];
    const float* w2  = (const float*)d_in[3];
    const float* sw1 = (const float*)d_in[4];
    const float* sw2 = (const float*)d_in[5];
    float* out = (float*)d_out;

    cudaFuncSetAttribute(moe_mma_kernel<true>,
                         cudaFuncAttributeMaxDynamicSharedMemorySize, SMEM_SZ);
    cudaFuncSetAttribute(moe_mma_kernel<false>,
                         cudaFuncAttributeMaxDynamicSharedMemorySize, SMEM_SZ);

    zero_cnt_kernel<<<1, 32>>>();
    router_kernel<<<T / 8, 256>>>(x, rw);
    cvt_x_kernel<<<(T * D / 4) / 256, 256>>>(x);
    tcvt_w1_kernel<<<dim3(H / 32, D / 64, NE), dim3(32, 8)>>>(w1, sw1);
    tcvt_w2_kernel<<<dim3(D / 32, H / 64, NE), dim3(32, 8)>>>(w2, sw2);

    moe_mma_kernel<true><<<dim3(H / TN, T / TM, NE), NTHR, SMEM_SZ>>>();
    moe_mma_kernel<false><<<dim3(D / TN, T / TM, NE), NTHR, SMEM_SZ>>>();

    combine_kernel<<<T, 256>>>(out);
}

// round 16
// speedup vs baseline: 1.1434x; 1.0646x over previous
#include <cuda_runtime.h>
#include <cuda_fp16.h>
#include <math.h>
#include <stdint.h>

// Problem constants
#define T 8192
#define D 1024
#define H 4096
#define E 8
#define NE 9        // 8 routed + shared pseudo-expert

// GEMM tiling
#define TM 128
#define TN 128
#define KC 64       // fp16 K elements per chunk: 128B rows (SW128 swizzle)

// SMEM layout (relative to 1024-aligned base)
#define OFF_ROWA  0          // int[128]
#define OFF_ROWS  512        // int[128]
#define OFF_W     1024       // float[128]
#define OFF_A     2048       // 2 x 16KB
#define OFF_B     34816      // 2 x 16KB
#define SMEM_CORE 67584
#define SMEM_SZ   (SMEM_CORE + 1024)

#define SWZ(off) ((off) ^ (((off) >> 3) & 0x70))

// ---------------- static device scratch (allocation-free) -------------------
__device__ int    g_cnt[NE];
__device__ int    g_pair_tok[NE * T];
__device__ int    g_pair_hidx[NE * T];
__device__ float  g_pair_w[NE * T];
__device__ __half g_xh[(size_t)T * D];         // x fp16  [T][D]
__device__ __half g_w1t[(size_t)NE * H * D];   // per e: [H][D] K-major
__device__ __half g_w2t[(size_t)NE * D * H];   // per e: [D][H] K-major
__device__ __half g_h[(size_t)T * 3 * H];      // activations fp16 (weight-folded)
__device__ float  g_po[(size_t)T * 3 * D];     // per-pair down-proj output

// ---------------- PTX helpers ------------------------------------------------
__device__ __forceinline__ uint32_t smem_u32(const void* p) {
    uint32_t a;
    asm("{ .reg .u64 t; cvta.to.shared.u64 t, %1; cvt.u32.u64 %0, t; }"
        : "=r"(a) : "l"(p));
    return a;
}
#define CP16(s, g) \
    asm volatile("cp.async.cg.shared.global [%0], [%1], 16;" \
                 :: "r"(s), "l"(g) : "memory")
#define CP_COMMIT() asm volatile("cp.async.commit_group;" ::: "memory")
#define CP_WAIT1()  asm volatile("cp.async.wait_group 1;" ::: "memory")
#define CP_WAIT0()  asm volatile("cp.async.wait_group 0;" ::: "memory")

#define LDSM_X4(d0, d1, d2, d3, a) \
    asm volatile("ldmatrix.sync.aligned.m8n8.x4.shared.b16 {%0,%1,%2,%3}, [%4];" \
                 : "=r"(d0), "=r"(d1), "=r"(d2), "=r"(d3) : "r"(a))

__device__ __forceinline__ void mma16816(float* c, const uint32_t* a,
                                         const uint32_t* b) {
    asm volatile(
        "mma.sync.aligned.m16n8k16.row.col.f32.f16.f16.f32 "
        "{%0,%1,%2,%3}, {%4,%5,%6,%7}, {%8,%9}, {%0,%1,%2,%3};"
        : "+f"(c[0]), "+f"(c[1]), "+f"(c[2]), "+f"(c[3])
        : "r"(a[0]), "r"(a[1]), "r"(a[2]), "r"(a[3]), "r"(b[0]), "r"(b[1]));
}

// ---------------- kernel: x -> fp16 (+ counter init in block 0) -------------
__global__ void cvt_x_kernel(const float* __restrict__ x) {
    if (blockIdx.x == 0 && threadIdx.x < NE)
        g_cnt[threadIdx.x] = (threadIdx.x == E) ? T : 0;
    int i = blockIdx.x * blockDim.x + threadIdx.x;   // over T*D/4
    float4 v = ((const float4*)x)[i];
    __half2* o = (__half2*)g_xh;
    o[i * 2 + 0] = __floats2half2_rn(v.x, v.y);
    o[i * 2 + 1] = __floats2half2_rn(v.z, v.w);
}

// ---------------- kernel: router (warp per token) ----------------------------
__global__ void router_kernel(const float* __restrict__ x,
                              const float* __restrict__ rw) {
    int warp = (blockIdx.x * blockDim.x + threadIdx.x) >> 5;
    int lane = threadIdx.x & 31;
    if (warp >= T) return;

    const float* xr = x + (size_t)warp * D;
    float acc[E];
#pragma unroll
    for (int e = 0; e < E; e++) acc[e] = 0.f;

    for (int d = lane; d < D; d += 32) {
        float xv = xr[d];
        const float4* r4 = (const float4*)(rw + (size_t)d * E);
        float4 r0 = r4[0], r1 = r4[1];
        acc[0] += xv * r0.x; acc[1] += xv * r0.y;
        acc[2] += xv * r0.z; acc[3] += xv * r0.w;
        acc[4] += xv * r1.x; acc[5] += xv * r1.y;
        acc[6] += xv * r1.z; acc[7] += xv * r1.w;
    }
#pragma unroll
    for (int o = 16; o; o >>= 1)
#pragma unroll
        for (int e = 0; e < E; e++)
            acc[e] += __shfl_xor_sync(0xFFFFFFFFu, acc[e], o);

    if (lane == 0) {
        float mx = acc[0];
#pragma unroll
        for (int e = 1; e < E; e++) mx = fmaxf(mx, acc[e]);
        float p[E];
#pragma unroll
        for (int e = 0; e < E; e++) p[e] = expf(acc[e] - mx);

        int i0 = 0; float v0 = p[0];
#pragma unroll
        for (int e = 1; e < E; e++) if (p[e] > v0) { v0 = p[e]; i0 = e; }
        int i1 = (i0 == 0) ? 1 : 0; float v1 = p[i1];
#pragma unroll
        for (int e = 0; e < E; e++)
            if (e != i0 && p[e] > v1) { v1 = p[e]; i1 = e; }

        float s = v0 + v1;
        float w0 = v0 / s, w1 = v1 / s;

        int s0 = atomicAdd(&g_cnt[i0], 1);
        g_pair_tok [i0 * T + s0] = warp;
        g_pair_hidx[i0 * T + s0] = warp * 3 + 0;
        g_pair_w   [i0 * T + s0] = w0;

        int s1 = atomicAdd(&g_cnt[i1], 1);
        g_pair_tok [i1 * T + s1] = warp;
        g_pair_hidx[i1 * T + s1] = warp * 3 + 1;
        g_pair_w   [i1 * T + s1] = w1;

        g_pair_tok [E * T + warp] = warp;
        g_pair_hidx[E * T + warp] = warp * 3 + 2;
        g_pair_w   [E * T + warp] = 1.0f;
    }
}

// ---------------- kernels: transpose+convert weights to fp16 K-major --------
// 64(r) x 32(c) input tile; half2 stores give full 128B-line output coverage.
__device__ __forceinline__ void transpose_tile(const float* __restrict__ in,
                                               __half* __restrict__ outp,
                                               int R, int C) {
    __shared__ float tile[64][33];
    int c0 = blockIdx.x * 32, r0 = blockIdx.y * 64;
    int tx = threadIdx.x, ty = threadIdx.y;   // block (32, 8)
#pragma unroll
    for (int j = 0; j < 64; j += 8)
        tile[ty + j][tx] = in[(size_t)(r0 + ty + j) * C + (c0 + tx)];
    __syncthreads();
    int base = ty * 32 + tx;
#pragma unroll
    for (int s = 0; s < 4; s++) {
        int idx = s * 256 + base;         // 0..1023
        int oc = idx >> 5;                // 0..31
        int k  = idx & 31;                // 0..31 -> r pairs
        __half2 v = __floats2half2_rn(tile[2 * k][oc], tile[2 * k + 1][oc]);
        *(__half2*)(outp + (size_t)(c0 + oc) * R + r0 + 2 * k) = v;
    }
}
__global__ void tcvt_w1_kernel(const float* __restrict__ w1,
                               const float* __restrict__ sw1) {
    int e = blockIdx.z;
    const float* in = (e < E) ? (w1 + (size_t)e * D * H) : sw1;  // [D, H]
    transpose_tile(in, g_w1t + (size_t)e * H * D, D, H);          // -> [H, D]
}
__global__ void tcvt_w2_kernel(const float* __restrict__ w2,
                               const float* __restrict__ sw2) {
    int e = blockIdx.z;
    const float* in = (e < E) ? (w2 + (size_t)e * H * D) : sw2;  // [H, D]
    transpose_tile(in, g_w2t + (size_t)e * D * H, H, D);          // -> [D, H]
}

// ---------------- main grouped HMMA GEMM -------------------------------------
// UP:  g_h[hidx, n] = w * silu( xh[tok, :] . w1t[e][n, :] ),  K = D
// DN:  g_po[hidx, n] = g_h[hidx, :] . w2t[e][n, :],           K = H
// Tile: 128x128, 256 threads (2x4 warps, warp tile 64x32), dual-buffer cp.async.
template <bool UP>
__global__ void __launch_bounds__(256, 2) moe_mma_kernel() {
    constexpr int KDIM = UP ? D : H;
    constexpr int NC = KDIM / KC;

    extern __shared__ char smem_raw[];

    const int e = blockIdx.z;
    const int cnt = g_cnt[e];
    const int m0 = blockIdx.y * TM;
    if (m0 >= cnt) return;
    const int n0 = blockIdx.x * TN;

    const int tid = threadIdx.x, wid = tid >> 5, lane = tid & 31;
    const int grp = lane >> 2, qp = lane & 3;
    const int warp_m = (wid & 1) * 64;     // 2 warps along M (64 rows each)
    const int warp_n = (wid >> 1) * 32;    // 4 warps along N (32 cols each)

    uint32_t sb_raw = smem_u32(smem_raw);
    uint32_t sb = (sb_raw + 1023u) & ~1023u;
    char* sm = smem_raw + (sb - sb_raw);

    int*   rowA = (int*)(sm + OFF_ROWA);
    int*   rowS = (int*)(sm + OFF_ROWS);
    float* rowW = (float*)(sm + OFF_W);
    for (int i = tid; i < TM; i += 256) {
        int m = m0 + i;
        int idx = e * T + ((m < cnt) ? m : m0);   // clamp to a valid row
        if (UP) {
            rowA[i] = g_pair_tok[idx];
            rowS[i] = g_pair_hidx[idx];
            rowW[i] = g_pair_w[idx];
        } else {
            rowA[i] = g_pair_hidx[idx];
        }
    }
    __syncthreads();

    const __half* Abase = UP ? g_xh : g_h;
    const __half* Bexp  = (UP ? g_w1t : g_w2t) + (size_t)e * ((size_t)H * D);

    const int lr = tid >> 3, lch = tid & 7;   // 32 load rows per pass, 8 chunks

    // --- ldmatrix per-lane address precompute (SW128 swizzle) ---
    const uint32_t asub = (uint32_t)((lane >> 4) << 4);
    uint32_t arel[4], amask[4];
#pragma unroll
    for (int mt = 0; mt < 4; mt++) {
        uint32_t rr = (uint32_t)((warp_m + mt * 16 + (lane & 15)) * 128);
        arel[mt] = rr;
        amask[mt] = (rr >> 3) & 0x70;
    }
    const int brow = (lane & 7) | ((lane >> 4) << 3);
    const uint32_t bsub = (uint32_t)(((lane >> 3) & 1) << 4);
    uint32_t brel[2], bmask[2];
#pragma unroll
    for (int g = 0; g < 2; g++) {
        uint32_t rr = (uint32_t)((warp_n + g * 16 + brow) * 128);
        brel[g] = rr;
        bmask[g] = (rr >> 3) & 0x70;
    }

    float acc[4][4][4];
#pragma unroll
    for (int mt = 0; mt < 4; mt++)
#pragma unroll
        for (int nt = 0; nt < 4; nt++)
#pragma unroll
            for (int k = 0; k < 4; k++) acc[mt][nt][k] = 0.f;

    // prologue: chunk 0 -> buffer 0
    {
        uint32_t sA = sb + OFF_A, sBb = sb + OFF_B;
#pragma unroll
        for (int it = 0; it < 4; it++) {
            int r = lr + it * 32;
            uint32_t o = SWZ((uint32_t)(r * 128 + lch * 16));
            CP16(sA + o, Abase + (size_t)rowA[r] * KDIM + lch * 8);
            CP16(sBb + o, Bexp + (size_t)(n0 + r) * KDIM + lch * 8);
        }
        CP_COMMIT();
    }

#pragma unroll 1
    for (int c = 0; c < NC; c++) {
        const int buf = c & 1;
        if (c + 1 < NC) {
            uint32_t sA = sb + OFF_A + (buf ^ 1) * 16384;
            uint32_t sBb = sb + OFF_B + (buf ^ 1) * 16384;
            const int kb = (c + 1) * KC;
#pragma unroll
            for (int it = 0; it < 4; it++) {
                int r = lr + it * 32;
                uint32_t o = SWZ((uint32_t)(r * 128 + lch * 16));
                CP16(sA + o, Abase + (size_t)rowA[r] * KDIM + kb + lch * 8);
                CP16(sBb + o, Bexp + (size_t)(n0 + r) * KDIM + kb + lch * 8);
            }
            CP_COMMIT();
            CP_WAIT1();
        } else {
            CP_WAIT0();
        }
        __syncthreads();

        const uint32_t aB = sb + OFF_A + buf * 16384;
        const uint32_t bB = sb + OFF_B + buf * 16384;
#pragma unroll
        for (int k16 = 0; k16 < 4; k16++) {
            const uint32_t kby = (uint32_t)(k16 * 32);
            uint32_t bq[4][2];
            {
                uint32_t r0, r1, r2, r3;
                LDSM_X4(r0, r1, r2, r3, bB + brel[0] + ((kby + bsub) ^ bmask[0]));
                bq[0][0] = r0; bq[0][1] = r1; bq[1][0] = r2; bq[1][1] = r3;
                LDSM_X4(r0, r1, r2, r3, bB + brel[1] + ((kby + bsub) ^ bmask[1]));
                bq[2][0] = r0; bq[2][1] = r1; bq[3][0] = r2; bq[3][1] = r3;
            }
#pragma unroll
            for (int mt = 0; mt < 4; mt++) {
                uint32_t af[4];
                LDSM_X4(af[0], af[1], af[2], af[3],
                        aB + arel[mt] + ((kby + asub) ^ amask[mt]));
#pragma unroll
                for (int nt = 0; nt < 4; nt++)
                    mma16816(acc[mt][nt], af, bq[nt]);
            }
        }
        __syncthreads();
    }

    // ---- epilogue ----
    if (UP) {
#pragma unroll
        for (int mt = 0; mt < 4; mt++) {
#pragma unroll
            for (int hf = 0; hf < 2; hf++) {
                int mi = warp_m + mt * 16 + grp + hf * 8;
                if (m0 + mi < cnt) {
                    float w = rowW[mi];
                    __half* dst = g_h + (size_t)rowS[mi] * H + n0 + warp_n + qp * 2;
#pragma unroll
                    for (int nt = 0; nt < 4; nt++) {
                        float y0 = acc[mt][nt][hf * 2 + 0];
                        float y1 = acc[mt][nt][hf * 2 + 1];
                        __half2 v = __floats2half2_rn(w * (y0 / (1.f + __expf(-y0))),
                                                      w * (y1 / (1.f + __expf(-y1))));
                        *(__half2*)(dst + nt * 8) = v;
                    }
                }
            }
        }
    } else {
#pragma unroll
        for (int mt = 0; mt < 4; mt++) {
#pragma unroll
            for (int hf = 0; hf < 2; hf++) {
                int mi = warp_m + mt * 16 + grp + hf * 8;
                if (m0 + mi < cnt) {
                    float* dst = g_po + (size_t)rowA[mi] * D + n0 + warp_n + qp * 2;
#pragma unroll
                    for (int nt = 0; nt < 4; nt++) {
                        float2 v = make_float2(acc[mt][nt][hf * 2 + 0],
                                               acc[mt][nt][hf * 2 + 1]);
                        *(float2*)(dst + nt * 8) = v;
                    }
                }
            }
        }
    }
}

// ---------------- kernel: combine 3 pair-rows per token ----------------------
__global__ void combine_kernel(float* __restrict__ out) {
    int t = blockIdx.x, r = threadIdx.x;      // 256 threads, D/4 float4s
    const float4* po = (const float4*)g_po;
    size_t b = (size_t)t * 768;               // 3 rows * 256 float4
    float4 a = po[b + r];
    float4 c = po[b + 256 + r];
    float4 d = po[b + 512 + r];
    ((float4*)out)[(size_t)t * 256 + r] =
        make_float4(a.x + c.x + d.x, a.y + c.y + d.y,
                    a.z + c.z + d.z, a.w + c.w + d.w);
}

// ---------------- launch -----------------------------------------------------
extern "C" void kernel_launch(void* const* d_in, const int* in_sizes, int n_in,
                              void* d_out, int out_size) {
    const float* x   = (const float*)d_in[0];
    const float* rw  = (const float*)d_in[1];
    const float* w1  = (const float*)d_in[2];
    const float* w2  = (const float*)d_in[3];
    const float* sw1 = (const float*)d_in[4];
    const float* sw2 = (const float*)d_in[5];
    float* out = (float*)d_out;

    cudaFuncSetAttribute(moe_mma_kernel<true>,
                         cudaFuncAttributeMaxDynamicSharedMemorySize, SMEM_SZ);
    cudaFuncSetAttribute(moe_mma_kernel<false>,
                         cudaFuncAttributeMaxDynamicSharedMemorySize, SMEM_SZ);

    cvt_x_kernel<<<(T * D / 4) / 256, 256>>>(x);     // also resets g_cnt
    router_kernel<<<T / 8, 256>>>(x, rw);
    tcvt_w1_kernel<<<dim3(H / 32, D / 64, NE), dim3(32, 8)>>>(w1, sw1);
    tcvt_w2_kernel<<<dim3(D / 32, H / 64, NE), dim3(32, 8)>>>(w2, sw2);

    moe_mma_kernel<true><<<dim3(H / TN, T / TM, NE), 256, SMEM_SZ>>>();
    moe_mma_kernel<false><<<dim3(D / TN, T / TM, NE), 256, SMEM_SZ>>>();

    combine_kernel<<<T, 256>>>(out);
}

// round 17
// speedup vs baseline: 1.1435x; 1.0000x over previous
#include <cuda_runtime.h>
#include <cuda_fp16.h>
#include <math.h>
#include <stdint.h>

// Problem constants
#define T 8192
#define D 1024
#define H 4096
#define E 8
#define NE 9        // 8 routed + shared pseudo-expert

// GEMM tiling
#define TM 128
#define TN 128
#define KC 64       // fp16 K elements per chunk: 128B rows (SW128 swizzle)

// SMEM layout (relative to 1024-aligned base)
#define OFF_ROWA  0          // int[128]
#define OFF_ROWS  512        // int[128]
#define OFF_W     1024       // float[128]
#define OFF_A     2048       // 2 x 16KB
#define OFF_B     34816      // 2 x 16KB
#define SMEM_CORE 67584
#define SMEM_SZ   (SMEM_CORE + 1024)

#define SWZ(off) ((off) ^ (((off) >> 3) & 0x70))

// ---------------- static device scratch (allocation-free) -------------------
__device__ int    g_cnt[NE];
__device__ int    g_pair_tok[NE * T];
__device__ int    g_pair_hidx[NE * T];
__device__ float  g_pair_w[NE * T];
__device__ __half g_xh[(size_t)T * D];         // x fp16  [T][D]
__device__ __half g_w1t[(size_t)NE * H * D];   // per e: [H][D] K-major
__device__ __half g_w2t[(size_t)NE * D * H];   // per e: [D][H] K-major
__device__ __half g_h[(size_t)T * 3 * H];      // activations fp16 (weight-folded)
__device__ float  g_po[(size_t)T * 3 * D];     // per-pair down-proj output

// ---------------- PTX helpers ------------------------------------------------
__device__ __forceinline__ uint32_t smem_u32(const void* p) {
    uint32_t a;
    asm("{ .reg .u64 t; cvta.to.shared.u64 t, %1; cvt.u32.u64 %0, t; }"
        : "=r"(a) : "l"(p));
    return a;
}
#define CP16(s, g) \
    asm volatile("cp.async.cg.shared.global [%0], [%1], 16;" \
                 :: "r"(s), "l"(g) : "memory")
#define CP_COMMIT() asm volatile("cp.async.commit_group;" ::: "memory")
#define CP_WAIT1()  asm volatile("cp.async.wait_group 1;" ::: "memory")
#define CP_WAIT0()  asm volatile("cp.async.wait_group 0;" ::: "memory")

#define LDSM_X4(d0, d1, d2, d3, a) \
    asm volatile("ldmatrix.sync.aligned.m8n8.x4.shared.b16 {%0,%1,%2,%3}, [%4];" \
                 : "=r"(d0), "=r"(d1), "=r"(d2), "=r"(d3) : "r"(a))

__device__ __forceinline__ void mma16816(float* c, const uint32_t* a,
                                         const uint32_t* b) {
    asm volatile(
        "mma.sync.aligned.m16n8k16.row.col.f32.f16.f16.f32 "
        "{%0,%1,%2,%3}, {%4,%5,%6,%7}, {%8,%9}, {%0,%1,%2,%3};"
        : "+f"(c[0]), "+f"(c[1]), "+f"(c[2]), "+f"(c[3])
        : "r"(a[0]), "r"(a[1]), "r"(a[2]), "r"(a[3]), "r"(b[0]), "r"(b[1]));
}

// ---------------- kernel: x -> fp16 (+ counter init in block 0) -------------
__global__ void cvt_x_kernel(const float* __restrict__ x) {
    if (blockIdx.x == 0 && threadIdx.x < NE)
        g_cnt[threadIdx.x] = (threadIdx.x == E) ? T : 0;
    int i = blockIdx.x * blockDim.x + threadIdx.x;   // over T*D/4
    float4 v = ((const float4*)x)[i];
    __half2* o = (__half2*)g_xh;
    o[i * 2 + 0] = __floats2half2_rn(v.x, v.y);
    o[i * 2 + 1] = __floats2half2_rn(v.z, v.w);
}

// ---------------- kernel: router (warp per token) ----------------------------
__global__ void router_kernel(const float* __restrict__ x,
                              const float* __restrict__ rw) {
    int warp = (blockIdx.x * blockDim.x + threadIdx.x) >> 5;
    int lane = threadIdx.x & 31;
    if (warp >= T) return;

    const float* xr = x + (size_t)warp * D;
    float acc[E];
#pragma unroll
    for (int e = 0; e < E; e++) acc[e] = 0.f;

    for (int d = lane; d < D; d += 32) {
        float xv = xr[d];
        const float4* r4 = (const float4*)(rw + (size_t)d * E);
        float4 r0 = r4[0], r1 = r4[1];
        acc[0] += xv * r0.x; acc[1] += xv * r0.y;
        acc[2] += xv * r0.z; acc[3] += xv * r0.w;
        acc[4] += xv * r1.x; acc[5] += xv * r1.y;
        acc[6] += xv * r1.z; acc[7] += xv * r1.w;
    }
#pragma unroll
    for (int o = 16; o; o >>= 1)
#pragma unroll
        for (int e = 0; e < E; e++)
            acc[e] += __shfl_xor_sync(0xFFFFFFFFu, acc[e], o);

    if (lane == 0) {
        float mx = acc[0];
#pragma unroll
        for (int e = 1; e < E; e++) mx = fmaxf(mx, acc[e]);
        float p[E];
#pragma unroll
        for (int e = 0; e < E; e++) p[e] = expf(acc[e] - mx);

        int i0 = 0; float v0 = p[0];
#pragma unroll
        for (int e = 1; e < E; e++) if (p[e] > v0) { v0 = p[e]; i0 = e; }
        int i1 = (i0 == 0) ? 1 : 0; float v1 = p[i1];
#pragma unroll
        for (int e = 0; e < E; e++)
            if (e != i0 && p[e] > v1) { v1 = p[e]; i1 = e; }

        float s = v0 + v1;
        float w0 = v0 / s, w1 = v1 / s;

        int s0 = atomicAdd(&g_cnt[i0], 1);
        g_pair_tok [i0 * T + s0] = warp;
        g_pair_hidx[i0 * T + s0] = warp * 3 + 0;
        g_pair_w   [i0 * T + s0] = w0;

        int s1 = atomicAdd(&g_cnt[i1], 1);
        g_pair_tok [i1 * T + s1] = warp;
        g_pair_hidx[i1 * T + s1] = warp * 3 + 1;
        g_pair_w   [i1 * T + s1] = w1;

        g_pair_tok [E * T + warp] = warp;
        g_pair_hidx[E * T + warp] = warp * 3 + 2;
        g_pair_w   [E * T + warp] = 1.0f;
    }
}

// ---------------- kernels: transpose+convert weights to fp16 K-major --------
// 64(r) x 32(c) input tile; half2 stores give full 128B-line output coverage.
__device__ __forceinline__ void transpose_tile(const float* __restrict__ in,
                                               __half* __restrict__ outp,
                                               int R, int C) {
    __shared__ float tile[64][33];
    int c0 = blockIdx.x * 32, r0 = blockIdx.y * 64;
    int tx = threadIdx.x, ty = threadIdx.y;   // block (32, 8)
#pragma unroll
    for (int j = 0; j < 64; j += 8)
        tile[ty + j][tx] = in[(size_t)(r0 + ty + j) * C + (c0 + tx)];
    __syncthreads();
    int base = ty * 32 + tx;
#pragma unroll
    for (int s = 0; s < 4; s++) {
        int idx = s * 256 + base;         // 0..1023
        int oc = idx >> 5;                // 0..31
        int k  = idx & 31;                // 0..31 -> r pairs
        __half2 v = __floats2half2_rn(tile[2 * k][oc], tile[2 * k + 1][oc]);
        *(__half2*)(outp + (size_t)(c0 + oc) * R + r0 + 2 * k) = v;
    }
}
__global__ void tcvt_w1_kernel(const float* __restrict__ w1,
                               const float* __restrict__ sw1) {
    int e = blockIdx.z;
    const float* in = (e < E) ? (w1 + (size_t)e * D * H) : sw1;  // [D, H]
    transpose_tile(in, g_w1t + (size_t)e * H * D, D, H);          // -> [H, D]
}
__global__ void tcvt_w2_kernel(const float* __restrict__ w2,
                               const float* __restrict__ sw2) {
    int e = blockIdx.z;
    const float* in = (e < E) ? (w2 + (size_t)e * H * D) : sw2;  // [H, D]
    transpose_tile(in, g_w2t + (size_t)e * D * H, H, D);          // -> [D, H]
}

// ---------------- main grouped HMMA GEMM -------------------------------------
// UP:  g_h[hidx, n] = w * silu( xh[tok, :] . w1t[e][n, :] ),  K = D
// DN:  g_po[hidx, n] = g_h[hidx, :] . w2t[e][n, :],           K = H
// Tile: 128x128, 256 threads (2x4 warps, warp tile 64x32), dual-buffer cp.async.
template <bool UP>
__global__ void __launch_bounds__(256, 2) moe_mma_kernel() {
    constexpr int KDIM = UP ? D : H;
    constexpr int NC = KDIM / KC;

    extern __shared__ char smem_raw[];

    const int e = blockIdx.z;
    const int cnt = g_cnt[e];
    const int m0 = blockIdx.y * TM;
    if (m0 >= cnt) return;
    const int n0 = blockIdx.x * TN;

    const int tid = threadIdx.x, wid = tid >> 5, lane = tid & 31;
    const int grp = lane >> 2, qp = lane & 3;
    const int warp_m = (wid & 1) * 64;     // 2 warps along M (64 rows each)
    const int warp_n = (wid >> 1) * 32;    // 4 warps along N (32 cols each)

    uint32_t sb_raw = smem_u32(smem_raw);
    uint32_t sb = (sb_raw + 1023u) & ~1023u;
    char* sm = smem_raw + (sb - sb_raw);

    int*   rowA = (int*)(sm + OFF_ROWA);
    int*   rowS = (int*)(sm + OFF_ROWS);
    float* rowW = (float*)(sm + OFF_W);
    for (int i = tid; i < TM; i += 256) {
        int m = m0 + i;
        int idx = e * T + ((m < cnt) ? m : m0);   // clamp to a valid row
        if (UP) {
            rowA[i] = g_pair_tok[idx];
            rowS[i] = g_pair_hidx[idx];
            rowW[i] = g_pair_w[idx];
        } else {
            rowA[i] = g_pair_hidx[idx];
        }
    }
    __syncthreads();

    const __half* Abase = UP ? g_xh : g_h;
    const __half* Bexp  = (UP ? g_w1t : g_w2t) + (size_t)e * ((size_t)H * D);

    const int lr = tid >> 3, lch = tid & 7;   // 32 load rows per pass, 8 chunks

    // --- ldmatrix per-lane address precompute (SW128 swizzle) ---
    const uint32_t asub = (uint32_t)((lane >> 4) << 4);
    uint32_t arel[4], amask[4];
#pragma unroll
    for (int mt = 0; mt < 4; mt++) {
        uint32_t rr = (uint32_t)((warp_m + mt * 16 + (lane & 15)) * 128);
        arel[mt] = rr;
        amask[mt] = (rr >> 3) & 0x70;
    }
    const int brow = (lane & 7) | ((lane >> 4) << 3);
    const uint32_t bsub = (uint32_t)(((lane >> 3) & 1) << 4);
    uint32_t brel[2], bmask[2];
#pragma unroll
    for (int g = 0; g < 2; g++) {
        uint32_t rr = (uint32_t)((warp_n + g * 16 + brow) * 128);
        brel[g] = rr;
        bmask[g] = (rr >> 3) & 0x70;
    }

    float acc[4][4][4];
#pragma unroll
    for (int mt = 0; mt < 4; mt++)
#pragma unroll
        for (int nt = 0; nt < 4; nt++)
#pragma unroll
            for (int k = 0; k < 4; k++) acc[mt][nt][k] = 0.f;

    // prologue: chunk 0 -> buffer 0
    {
        uint32_t sA = sb + OFF_A, sBb = sb + OFF_B;
#pragma unroll
        for (int it = 0; it < 4; it++) {
            int r = lr + it * 32;
            uint32_t o = SWZ((uint32_t)(r * 128 + lch * 16));
            CP16(sA + o, Abase + (size_t)rowA[r] * KDIM + lch * 8);
            CP16(sBb + o, Bexp + (size_t)(n0 + r) * KDIM + lch * 8);
        }
        CP_COMMIT();
    }

#pragma unroll 1
    for (int c = 0; c < NC; c++) {
        const int buf = c & 1;
        if (c + 1 < NC) {
            uint32_t sA = sb + OFF_A + (buf ^ 1) * 16384;
            uint32_t sBb = sb + OFF_B + (buf ^ 1) * 16384;
            const int kb = (c + 1) * KC;
#pragma unroll
            for (int it = 0; it < 4; it++) {
                int r = lr + it * 32;
                uint32_t o = SWZ((uint32_t)(r * 128 + lch * 16));
                CP16(sA + o, Abase + (size_t)rowA[r] * KDIM + kb + lch * 8);
                CP16(sBb + o, Bexp + (size_t)(n0 + r) * KDIM + kb + lch * 8);
            }
            CP_COMMIT();
            CP_WAIT1();
        } else {
            CP_WAIT0();
        }
        __syncthreads();

        const uint32_t aB = sb + OFF_A + buf * 16384;
        const uint32_t bB = sb + OFF_B + buf * 16384;
#pragma unroll
        for (int k16 = 0; k16 < 4; k16++) {
            const uint32_t kby = (uint32_t)(k16 * 32);
            uint32_t bq[4][2];
            {
                uint32_t r0, r1, r2, r3;
                LDSM_X4(r0, r1, r2, r3, bB + brel[0] + ((kby + bsub) ^ bmask[0]));
                bq[0][0] = r0; bq[0][1] = r1; bq[1][0] = r2; bq[1][1] = r3;
                LDSM_X4(r0, r1, r2, r3, bB + brel[1] + ((kby + bsub) ^ bmask[1]));
                bq[2][0] = r0; bq[2][1] = r1; bq[3][0] = r2; bq[3][1] = r3;
            }
#pragma unroll
            for (int mt = 0; mt < 4; mt++) {
                uint32_t af[4];
                LDSM_X4(af[0], af[1], af[2], af[3],
                        aB + arel[mt] + ((kby + asub) ^ amask[mt]));
#pragma unroll
                for (int nt = 0; nt < 4; nt++)
                    mma16816(acc[mt][nt], af, bq[nt]);
            }
        }
        __syncthreads();
    }

    // ---- epilogue ----
    if (UP) {
#pragma unroll
        for (int mt = 0; mt < 4; mt++) {
#pragma unroll
            for (int hf = 0; hf < 2; hf++) {
                int mi = warp_m + mt * 16 + grp + hf * 8;
                if (m0 + mi < cnt) {
                    float w = rowW[mi];
                    __half* dst = g_h + (size_t)rowS[mi] * H + n0 + warp_n + qp * 2;
#pragma unroll
                    for (int nt = 0; nt < 4; nt++) {
                        float y0 = acc[mt][nt][hf * 2 + 0];
                        float y1 = acc[mt][nt][hf * 2 + 1];
                        __half2 v = __floats2half2_rn(w * (y0 / (1.f + __expf(-y0))),
                                                      w * (y1 / (1.f + __expf(-y1))));
                        *(__half2*)(dst + nt * 8) = v;
                    }
                }
            }
        }
    } else {
#pragma unroll
        for (int mt = 0; mt < 4; mt++) {
#pragma unroll
            for (int hf = 0; hf < 2; hf++) {
                int mi = warp_m + mt * 16 + grp + hf * 8;
                if (m0 + mi < cnt) {
                    float* dst = g_po + (size_t)rowA[mi] * D + n0 + warp_n + qp * 2;
#pragma unroll
                    for (int nt = 0; nt < 4; nt++) {
                        float2 v = make_float2(acc[mt][nt][hf * 2 + 0],
                                               acc[mt][nt][hf * 2 + 1]);
                        *(float2*)(dst + nt * 8) = v;
                    }
                }
            }
        }
    }
}

// ---------------- kernel: combine 3 pair-rows per token ----------------------
__global__ void combine_kernel(float* __restrict__ out) {
    int t = blockIdx.x, r = threadIdx.x;      // 256 threads, D/4 float4s
    const float4* po = (const float4*)g_po;
    size_t b = (size_t)t * 768;               // 3 rows * 256 float4
    float4 a = po[b + r];
    float4 c = po[b + 256 + r];
    float4 d = po[b + 512 + r];
    ((float4*)out)[(size_t)t * 256 + r] =
        make_float4(a.x + c.x + d.x, a.y + c.y + d.y,
                    a.z + c.z + d.z, a.w + c.w + d.w);
}

// ---------------- launch -----------------------------------------------------
extern "C" void kernel_launch(void* const* d_in, const int* in_sizes, int n_in,
                              void* d_out, int out_size) {
    const float* x   = (const float*)d_in[0];
    const float* rw  = (const float*)d_in[1];
    const float* w1  = (const float*)d_in[2];
    const float* w2  = (const float*)d_in[3];
    const float* sw1 = (const float*)d_in[4];
    const float* sw2 = (const float*)d_in[5];
    float* out = (float*)d_out;

    cudaFuncSetAttribute(moe_mma_kernel<true>,
                         cudaFuncAttributeMaxDynamicSharedMemorySize, SMEM_SZ);
    cudaFuncSetAttribute(moe_mma_kernel<false>,
                         cudaFuncAttributeMaxDynamicSharedMemorySize, SMEM_SZ);

    cvt_x_kernel<<<(T * D / 4) / 256, 256>>>(x);     // also resets g_cnt
    router_kernel<<<T / 8, 256>>>(x, rw);
    tcvt_w1_kernel<<<dim3(H / 32, D / 64, NE), dim3(32, 8)>>>(w1, sw1);
    tcvt_w2_kernel<<<dim3(D / 32, H / 64, NE), dim3(32, 8)>>>(w2, sw2);

    moe_mma_kernel<true><<<dim3(H / TN, T / TM, NE), 256, SMEM_SZ>>>();
    moe_mma_kernel<false><<<dim3(D / TN, T / TM, NE), 256, SMEM_SZ>>>();

    combine_kernel<<<T, 256>>>(out);
}